// round 17
// baseline (speedup 1.0000x reference)
#include <cuda_runtime.h>

#define NB 8
#define NS 2048
#define NH 2
#define NT (NB*NS)        // 16384 tokens
#define NBH (NB*NH)       // 16 (batch, head) pairs
#define SPLITS 8
#define KPS 256           // keys per split
#define QBLK 128          // queries per CTA
#define NQBLK (NS/QBLK)   // 16
#define NGROUP 8          // query groups per CTA
#define GQ 16             // queries per group (4 warps x 4)

// log2(e) / sqrt(D) folded into q so scores feed ex2 directly
#define QSCALE 0.72134752044448169f

// Accumulators (zero at module load; quantum kernel re-zeroes after reading)
__device__ float4 g_accN[NT*NH];   // numerators, index = token*2 + head
__device__ float  g_accD[NT*NH];   // denominators

typedef unsigned long long ull;

// ---- packed f32x2 helpers ----
static __device__ __forceinline__ ull pack2(float a, float b) {
    ull r; asm("mov.b64 %0, {%1,%2};" : "=l"(r) : "f"(a), "f"(b)); return r;
}
static __device__ __forceinline__ void unpack2(ull v, float& a, float& b) {
    asm("mov.b64 {%0,%1}, %2;" : "=f"(a), "=f"(b) : "l"(v));
}
static __device__ __forceinline__ ull fma2p(ull a, ull b, ull c) {
    ull d; asm("fma.rn.f32x2 %0, %1, %2, %3;" : "=l"(d) : "l"(a), "l"(b), "l"(c)); return d;
}
static __device__ __forceinline__ ull mul2p(ull a, ull b) {
    ull d; asm("mul.rn.f32x2 %0, %1, %2;" : "=l"(d) : "l"(a), "l"(b)); return d;
}
static __device__ __forceinline__ float ex2f(float x) {
    float r; asm("ex2.approx.f32 %0, %1;" : "=f"(r) : "f"(x)); return r;
}
static __device__ __forceinline__ float rcpf(float x) {
    float r; asm("rcp.approx.f32 %0, %1;" : "=f"(r) : "f"(x)); return r;
}

// ============================================================
// Fused QKV + split-K attention, LANES = KEYS layout.
// grid = (NQBLK, SPLITS, NBH) = (16,8,16) = 2048 CTAs, 128 thr.
// - K/V natural float4/key in SMEM (no duplication).
// - Each warp: 4 warp-uniform queries (broadcast from sQ) x
//   KPS keys; lane l handles keys base+l and base+32+l
//   -> 4 conflict-free LDS.128 per 8 lane-scores (0.5/score,
//      half of the R6 broadcast scheme).
// - 8 groups of 16 queries per CTA; per group: SMEM scratch
//   transpose + octet shfl-tree + atomicAdd into g_acc.
// ============================================================
__global__ void __launch_bounds__(128, 7) attn_kernel(const float* __restrict__ x,
                                                      const float* __restrict__ Wq,
                                                      const float* __restrict__ Wk,
                                                      const float* __restrict__ Wv) {
    __shared__ float sWq[32], sWk[32], sWv[32];   // this head's 4 rows (4x8)
    __shared__ ulonglong2 sQ[QBLK];               // {q0,q1},{q2,q3} per query (2KB)
    __shared__ ulonglong2 sK[KPS];                // {k0,k1},{k2,k3} per key  (4KB)
    __shared__ ulonglong2 sV[KPS];                // {v0,v1},{v2,v3} per key  (4KB)
    __shared__ float4 scrN[GQ][32];               // per-group lane partials (8KB)
    __shared__ float  scrD[GQ][32];               // (2KB)

    const int bh    = blockIdx.z;
    const int split = blockIdx.y;
    const int tid   = threadIdx.x;
    const int b     = bh >> 1;
    const int h     = bh & 1;
    const int w     = tid >> 5;
    const int lane  = tid & 31;

    if (tid < 32) {
        sWq[tid] = Wq[h*32 + tid];
        sWk[tid] = Wk[h*32 + tid];
        sWv[tid] = Wv[h*32 + tid];
    }
    __syncthreads();

    const float4* x4 = (const float4*)x;

    // ---- compute one query per thread into sQ ----
    {
        int tq = b*NS + blockIdx.x*QBLK + tid;
        float4 a0 = x4[tq*2], a1 = x4[tq*2+1];
        float xr[8] = {a0.x,a0.y,a0.z,a0.w,a1.x,a1.y,a1.z,a1.w};
        float q[4];
#pragma unroll
        for (int d = 0; d < 4; d++) {
            float s = 0.f;
#pragma unroll
            for (int e = 0; e < 8; e++) s += xr[e] * sWq[d*8 + e];
            q[d] = s * QSCALE;
        }
        ulonglong2 t;
        t.x = pack2(q[0], q[1]); t.y = pack2(q[2], q[3]);
        sQ[tid] = t;
    }

    // ---- stage K/V: 2 keys per thread, natural float4 packing ----
    {
        int tokA = b*NS + split*KPS + 2*tid;
        float4 a0 = x4[tokA*2], a1 = x4[tokA*2+1];
        float4 b0 = x4[tokA*2+2], b1 = x4[tokA*2+3];
        float xra[8] = {a0.x,a0.y,a0.z,a0.w,a1.x,a1.y,a1.z,a1.w};
        float xrb[8] = {b0.x,b0.y,b0.z,b0.w,b1.x,b1.y,b1.z,b1.w};
        float kA[4], vA[4], kB[4], vB[4];
#pragma unroll
        for (int d = 0; d < 4; d++) {
            float ka = 0.f, va = 0.f, kb = 0.f, vb = 0.f;
#pragma unroll
            for (int e = 0; e < 8; e++) {
                float wk = sWk[d*8 + e], wv = sWv[d*8 + e];
                ka += xra[e] * wk;  va += xra[e] * wv;
                kb += xrb[e] * wk;  vb += xrb[e] * wv;
            }
            kA[d] = ka; vA[d] = va; kB[d] = kb; vB[d] = vb;
        }
        ulonglong2 t;
        t.x = pack2(kA[0], kA[1]); t.y = pack2(kA[2], kA[3]); sK[2*tid]   = t;
        t.x = pack2(kB[0], kB[1]); t.y = pack2(kB[2], kB[3]); sK[2*tid+1] = t;
        t.x = pack2(vA[0], vA[1]); t.y = pack2(vA[2], vA[3]); sV[2*tid]   = t;
        t.x = pack2(vB[0], vB[1]); t.y = pack2(vB[2], vB[3]); sV[2*tid+1] = t;
    }
    __syncthreads();

    // ---- groups of 16 queries (4 per warp, warp-uniform) ----
    for (int g = 0; g < NGROUP; g++) {
        ull q01[4], q23[4];
#pragma unroll
        for (int i = 0; i < 4; i++) {
            ulonglong2 qq = sQ[g*GQ + w*4 + i];   // broadcast LDS
            q01[i] = qq.x; q23[i] = qq.y;
        }

        ull a01[4] = {0,0,0,0}, a23[4] = {0,0,0,0};
        float den[4] = {0.f, 0.f, 0.f, 0.f};

#pragma unroll
        for (int it = 0; it < KPS/64; it++) {
            ulonglong2 kA = sK[it*64 + lane];        // conflict-free LDS.128
            ulonglong2 kB = sK[it*64 + 32 + lane];
            ulonglong2 vA = sV[it*64 + lane];
            ulonglong2 vB = sV[it*64 + 32 + lane];
#pragma unroll
            for (int i = 0; i < 4; i++) {
                ull mA = mul2p(q01[i], kA.x);
                ull mB = mul2p(q01[i], kB.x);
                mA = fma2p(q23[i], kA.y, mA);
                mB = fma2p(q23[i], kB.y, mB);
                float lA, hA, lB, hB;
                unpack2(mA, lA, hA);
                unpack2(mB, lB, hB);
                float wA = ex2f(lA + hA);
                float wB = ex2f(lB + hB);
                ull wwA = pack2(wA, wA);
                ull wwB = pack2(wB, wB);
                a01[i] = fma2p(wwA, vA.x, a01[i]);
                a23[i] = fma2p(wwA, vA.y, a23[i]);
                a01[i] = fma2p(wwB, vB.x, a01[i]);
                a23[i] = fma2p(wwB, vB.y, a23[i]);
                den[i] += wA + wB;
            }
        }

        // lane partials -> scratch (conflict-free STS)
#pragma unroll
        for (int i = 0; i < 4; i++) {
            float n0, n1, n2, n3;
            unpack2(a01[i], n0, n1);
            unpack2(a23[i], n2, n3);
            scrN[w*4 + i][lane] = make_float4(n0, n1, n2, n3);
            scrD[w*4 + i][lane] = den[i];
        }
        __syncthreads();

        // phase2: tid -> (query q = tid>>3, part = tid&7); each part
        // sums 4 lanes, then octet shfl-tree, part 0 atomics.
        {
            int q = tid >> 3, part = tid & 7;
            float s0 = 0.f, s1 = 0.f, s2 = 0.f, s3 = 0.f, sd = 0.f;
#pragma unroll
            for (int jj = 0; jj < 4; jj++) {
                int j = part + jj*8;
                float4 nn = scrN[q][j];
                s0 += nn.x; s1 += nn.y; s2 += nn.z; s3 += nn.w;
                sd += scrD[q][j];
            }
#pragma unroll
            for (int d = 4; d >= 1; d >>= 1) {
                s0 += __shfl_down_sync(0xFFFFFFFFu, s0, d);
                s1 += __shfl_down_sync(0xFFFFFFFFu, s1, d);
                s2 += __shfl_down_sync(0xFFFFFFFFu, s2, d);
                s3 += __shfl_down_sync(0xFFFFFFFFu, s3, d);
                sd += __shfl_down_sync(0xFFFFFFFFu, sd, d);
            }
            if (part == 0) {
                int sidx = blockIdx.x*QBLK + g*GQ + q;
                int a = (b*NS + sidx)*2 + h;
                float* pN = (float*)&g_accN[a];
                atomicAdd(pN + 0, s0);
                atomicAdd(pN + 1, s1);
                atomicAdd(pN + 2, s2);
                atomicAdd(pN + 3, s3);
                atomicAdd(&g_accD[a], sd);
            }
        }
        __syncthreads();
    }
}

// ============================================================
// Finalize (R11-proven, 4.5us): loads fired first, head pairs
// adjacent lanes (shfl_xor(1)), re-zero accumulators.
// z_w = prod_{u<=w} cos(o_u + o_{u&3}) (w>=1); z_0 = prod_{u=1..7}.
// ============================================================
__global__ void __launch_bounds__(256) quantum_kernel(const float* __restrict__ Wo,
                                                      float* __restrict__ out) {
    __shared__ float sWo[64];
    int tid = threadIdx.x;
    int gid = blockIdx.x * 256 + tid;   // = token*2 + head

    // fire the long-latency loads immediately
    float4 nn = g_accN[gid];
    float  dd = g_accD[gid];

    if (tid < 64) sWo[tid] = Wo[tid];
    __syncthreads();

    int h = gid & 1;
    float r = rcpf(dd);
    float o0 = nn.x*r, o1 = nn.y*r, o2 = nn.z*r, o3 = nn.w*r;

    // other head's o lives in the adjacent lane
    float p0 = __shfl_xor_sync(0xFFFFFFFFu, o0, 1);
    float p1 = __shfl_xor_sync(0xFFFFFFFFu, o1, 1);
    float p2 = __shfl_xor_sync(0xFFFFFFFFu, o2, 1);
    float p3 = __shfl_xor_sync(0xFFFFFFFFu, o3, 1);

    // c_u for this thread's u = h*4+d: arg = o_u + o_{u&3}
    float a0 = o0 + (h ? p0 : o0);
    float a1 = o1 + (h ? p1 : o1);
    float a2 = o2 + (h ? p2 : o2);
    float a3 = o3 + (h ? p3 : o3);
    float c0 = __cosf(a0), c1 = __cosf(a1), c2 = __cosf(a2), c3 = __cosf(a3);

    // gather all 8 c's
    float q0 = __shfl_xor_sync(0xFFFFFFFFu, c0, 1);
    float q1 = __shfl_xor_sync(0xFFFFFFFFu, c1, 1);
    float q2 = __shfl_xor_sync(0xFFFFFFFFu, c2, 1);
    float q3 = __shfl_xor_sync(0xFFFFFFFFu, c3, 1);
    float gc[8];
    gc[0] = h ? q0 : c0;  gc[1] = h ? q1 : c1;
    gc[2] = h ? q2 : c2;  gc[3] = h ? q3 : c3;
    gc[4] = h ? c0 : q0;  gc[5] = h ? c1 : q1;
    gc[6] = h ? c2 : q2;  gc[7] = h ? c3 : q3;

    // z products
    float z[8];
    float tp = gc[1];
    z[1] = gc[0] * tp;
#pragma unroll
    for (int w = 2; w < 8; w++) { tp *= gc[w]; z[w] = gc[0] * tp; }
    z[0] = tp;

    // this thread's 4 output features f = h*4+i
    float rr[4];
#pragma unroll
    for (int i = 0; i < 4; i++) {
        float sacc = 0.f;
#pragma unroll
        for (int qq = 0; qq < 8; qq++) sacc += z[qq] * sWo[(h*4 + i)*8 + qq];
        rr[i] = sacc;
    }
    ((float4*)out)[gid] = make_float4(rr[0], rr[1], rr[2], rr[3]);

    // restore zero-state for the next replay
    g_accN[gid] = make_float4(0.f, 0.f, 0.f, 0.f);
    g_accD[gid] = 0.f;
}

// ============================================================
extern "C" void kernel_launch(void* const* d_in, const int* in_sizes, int n_in,
                              void* d_out, int out_size) {
    const float* x  = (const float*)d_in[0];
    const float* Wq = (const float*)d_in[1];
    const float* Wk = (const float*)d_in[2];
    const float* Wv = (const float*)d_in[3];
    const float* Wo = (const float*)d_in[4];
    float* out = (float*)d_out;

    attn_kernel<<<dim3(NQBLK, SPLITS, NBH), 128>>>(x, Wq, Wk, Wv);
    quantum_kernel<<<NT*NH/256, 256>>>(Wo, out);
}